// round 12
// baseline (speedup 1.0000x reference)
#include <cuda_runtime.h>
#include <cstdint>

#define NR 512
#define NZ 512

__device__ float4 g_qt[NR * NZ];

__device__ __forceinline__ uint32_t smem_u32(const void* p) {
    uint32_t a;
    asm("{ .reg .u64 t; cvta.to.shared.u64 t, %1; cvt.u32.u64 %0, t; }" : "=r"(a) : "l"(p));
    return a;
}

__device__ __forceinline__ void bulk_g2s(uint32_t dst, const void* src, uint32_t bytes, uint32_t mbar) {
    asm volatile("cp.async.bulk.shared::cluster.global.mbarrier::complete_tx::bytes [%0], [%1], %2, [%3];"
                 :: "r"(dst), "l"(src), "r"(bytes), "r"(mbar) : "memory");
}

__device__ __forceinline__ void bulk_s2g(void* dst, uint32_t src, uint32_t bytes) {
    asm volatile("cp.async.bulk.global.shared::cta.bulk_group [%0], [%1], %2;"
                 :: "l"(dst), "r"(src), "r"(bytes) : "memory");
}

__global__ void __launch_bounds__(256) build_qt_kernel(const float* __restrict__ tt) {
    cudaTriggerProgrammaticLaunchCompletion();
    int t = blockIdx.x * blockDim.x + threadIdx.x;
    int ir = t >> 9;
    int iz = t & 511;
    if (ir >= NR - 1 || iz >= NZ - 1) return;
    float4 v;
    v.x = __ldg(tt + t);
    v.y = __ldg(tt + t + 1);
    v.z = __ldg(tt + t + NZ);
    v.w = __ldg(tt + t + NZ + 1);
    g_qt[t] = v;
}

// Streaming r/z/out moved to bulk-copy (async proxy) so the L1tex tag path
// serves ONLY the gathers. 256 float4-points per block, 8 blocks/SM overlap
// each other's TMA latency.
__global__ void __launch_bounds__(256) interp_kernel(
    const float* __restrict__ r,
    const float* __restrict__ z,
    float* __restrict__ out,
    int n4)
{
    __shared__ alignas(128) float4 s_r[256];
    __shared__ alignas(128) float4 s_z[256];
    __shared__ alignas(128) float4 s_o[256];
    __shared__ alignas(8) unsigned long long s_mbar;

    int tid = threadIdx.x;
    int bid = blockIdx.x;
    int base4 = bid * 256;
    int count4 = n4 - base4;
    if (count4 > 256) count4 = 256;
    uint32_t bytes = (uint32_t)count4 * 16u;

    uint32_t mbar = smem_u32(&s_mbar);
    if (tid == 0) {
        asm volatile("mbarrier.init.shared.b64 [%0], %1;" :: "r"(mbar), "r"(1u) : "memory");
        asm volatile("fence.proxy.async.shared::cta;" ::: "memory");
    }
    __syncthreads();

    if (tid == 0) {
        asm volatile("mbarrier.arrive.expect_tx.shared.b64 _, [%0], %1;"
                     :: "r"(mbar), "r"(2u * bytes) : "memory");
        bulk_g2s(smem_u32(s_r), r + (size_t)base4 * 4, bytes, mbar);
        bulk_g2s(smem_u32(s_z), z + (size_t)base4 * 4, bytes, mbar);
    }

    // Wait for both bulk loads (parity 0; barrier used once per block).
    {
        uint32_t done;
        asm volatile(
            "{\n\t.reg .pred p;\n\t"
            "mbarrier.try_wait.parity.acquire.cta.shared::cta.b64 p, [%1], 0;\n\t"
            "selp.b32 %0, 1, 0, p;\n\t}"
            : "=r"(done) : "r"(mbar) : "memory");
        while (!done) {
            asm volatile(
                "{\n\t.reg .pred p;\n\t"
                "mbarrier.try_wait.parity.acquire.cta.shared::cta.b64 p, [%1], 0, 0x989680;\n\t"
                "selp.b32 %0, 1, 0, p;\n\t}"
                : "=r"(done) : "r"(mbar) : "memory");
        }
    }

    bool active = (tid < count4);
    float fr[4], fz[4];
    int   idx[4];
    if (active) {
        float4 rv = s_r[tid];
        float4 zv = s_z[tid];
        float rr[4] = {rv.x, rv.y, rv.z, rv.w};
        float zz[4] = {zv.x, zv.y, zv.z, zv.w};
#pragma unroll
        for (int k = 0; k < 4; k++) {
            float frf = fminf(fmaxf(floorf(rr[k]), 0.0f), (float)(NR - 2));
            float fzf = fminf(fmaxf(floorf(zz[k]), 0.0f), (float)(NZ - 2));
            fr[k] = rr[k] - frf;
            fz[k] = zz[k] - fzf;
            idx[k] = (((int)frf) << 9) + (int)fzf;
        }
    }

    // Quad table must be fully built before gathering.
    cudaGridDependencySynchronize();

    if (active) {
        float res[4];
#pragma unroll
        for (int k = 0; k < 4; k++) {
            float4 q = __ldg(&g_qt[idx[k]]);
            float wr1 = fr[k], wr0 = 1.0f - fr[k];
            float wz1 = fz[k], wz0 = 1.0f - fz[k];
            res[k] = q.x * (wr0 * wz0)
                   + q.z * (wr1 * wz0)
                   + q.y * (wr0 * wz1)
                   + q.w * (wr1 * wz1);
        }
        float4 o;
        o.x = res[0]; o.y = res[1]; o.z = res[2]; o.w = res[3];
        s_o[tid] = o;
    }
    __syncthreads();

    if (tid == 0) {
        asm volatile("fence.proxy.async.shared::cta;" ::: "memory");
        bulk_s2g(out + (size_t)base4 * 4, smem_u32(s_o), bytes);
        asm volatile("cp.async.bulk.commit_group;" ::: "memory");
        asm volatile("cp.async.bulk.wait_group 0;" ::: "memory");
    }
}

extern "C" void kernel_launch(void* const* d_in, const int* in_sizes, int n_in,
                              void* d_out, int out_size) {
    const float* r  = (const float*)d_in[0];
    const float* z  = (const float*)d_in[1];
    const float* tt = (const float*)d_in[2];
    float* out = (float*)d_out;

    int n = in_sizes[0];          // 20,000,000
    int n4 = n / 4;               // 5,000,000

    build_qt_kernel<<<(NR * NZ) / 256, 256>>>(tt);

    int threads = 256;
    int blocks = (n4 + 255) / 256;   // 19532

    cudaLaunchAttribute attrs[1];
    attrs[0].id = cudaLaunchAttributeProgrammaticStreamSerialization;
    attrs[0].val.programmaticStreamSerializationAllowed = 1;

    cudaLaunchConfig_t cfg = {};
    cfg.gridDim = dim3((unsigned)blocks);
    cfg.blockDim = dim3((unsigned)threads);
    cfg.dynamicSmemBytes = 0;
    cfg.stream = 0;
    cfg.attrs = attrs;
    cfg.numAttrs = 1;

    cudaLaunchKernelEx(&cfg, interp_kernel, r, z, out, n4);
}

// round 13
// speedup vs baseline: 1.0674x; 1.0674x over previous
#include <cuda_runtime.h>

#define NR 512
#define NZ 512

// Quad table: qt[ir*512+iz] = (tt[ir][iz], tt[ir][iz+1], tt[ir+1][iz], tt[ir+1][iz+1])
// 4MB, L2-resident. Collapses the 4-corner gather into ONE 16B gather per point.
__device__ float4 g_qt[NR * NZ];

__global__ void __launch_bounds__(256) build_qt_kernel(const float* __restrict__ tt) {
    // Fire PDL completion immediately: interp launches and runs its prolog
    // while the table is being built; interp's griddepsync provides ordering.
    cudaTriggerProgrammaticLaunchCompletion();

    int t = blockIdx.x * blockDim.x + threadIdx.x;   // 262144
    int ir = t >> 9;
    int iz = t & 511;
    if (ir >= NR - 1 || iz >= NZ - 1) return;

    float4 v;
    v.x = __ldg(tt + t);            // Q11
    v.y = __ldg(tt + t + 1);        // Q12
    v.z = __ldg(tt + t + NZ);       // Q21
    v.w = __ldg(tt + t + NZ + 1);   // Q22
    g_qt[t] = v;
}

// 4 points/thread, regs=32, ~full occupancy: measured L1tex tag-path floor
// (~1 distinct 128B line per point; 85.7-86.9us invariant across 7 variants).
__global__ void __launch_bounds__(256) interp_kernel(
    const float* __restrict__ r,
    const float* __restrict__ z,
    float* __restrict__ out,
    int n4)
{
    int i = blockIdx.x * blockDim.x + threadIdx.x;
    if (i >= n4) {
        cudaGridDependencySynchronize();
        return;
    }

    float4 rv = reinterpret_cast<const float4*>(r)[i];
    float4 zv = reinterpret_cast<const float4*>(z)[i];

    float rr[4] = {rv.x, rv.y, rv.z, rv.w};
    float zz[4] = {zv.x, zv.y, zv.z, zv.w};

    float fr[4], fz[4];
    int   idx[4];
#pragma unroll
    for (int k = 0; k < 4; k++) {
        float frf = fminf(fmaxf(floorf(rr[k]), 0.0f), (float)(NR - 2));
        float fzf = fminf(fmaxf(floorf(zz[k]), 0.0f), (float)(NZ - 2));
        fr[k] = rr[k] - frf;
        fz[k] = zz[k] - fzf;
        idx[k] = (((int)frf) << 9) + (int)fzf;
    }

    // Quad table must be fully built before gathering.
    cudaGridDependencySynchronize();

    float res[4];
#pragma unroll
    for (int k = 0; k < 4; k++) {
        float4 q = __ldg(&g_qt[idx[k]]);
        float wr1 = fr[k], wr0 = 1.0f - fr[k];
        float wz1 = fz[k], wz0 = 1.0f - fz[k];
        res[k] = q.x * (wr0 * wz0)
               + q.z * (wr1 * wz0)
               + q.y * (wr0 * wz1)
               + q.w * (wr1 * wz1);
    }

    float4 o;
    o.x = res[0]; o.y = res[1]; o.z = res[2]; o.w = res[3];
    reinterpret_cast<float4*>(out)[i] = o;
}

extern "C" void kernel_launch(void* const* d_in, const int* in_sizes, int n_in,
                              void* d_out, int out_size) {
    const float* r  = (const float*)d_in[0];
    const float* z  = (const float*)d_in[1];
    const float* tt = (const float*)d_in[2];
    float* out = (float*)d_out;

    int n = in_sizes[0];          // 20,000,000
    int n4 = n / 4;               // 5,000,000

    build_qt_kernel<<<(NR * NZ) / 256, 256>>>(tt);

    int threads = 256;
    int blocks = (n4 + threads - 1) / threads;

    // PDL: interp launches as soon as build fires its trigger; device-side
    // griddepsync orders the quad-table reads after the build grid.
    cudaLaunchAttribute attrs[1];
    attrs[0].id = cudaLaunchAttributeProgrammaticStreamSerialization;
    attrs[0].val.programmaticStreamSerializationAllowed = 1;

    cudaLaunchConfig_t cfg = {};
    cfg.gridDim = dim3((unsigned)blocks);
    cfg.blockDim = dim3((unsigned)threads);
    cfg.dynamicSmemBytes = 0;
    cfg.stream = 0;
    cfg.attrs = attrs;
    cfg.numAttrs = 1;

    cudaLaunchKernelEx(&cfg, interp_kernel, r, z, out, n4);
}